// round 15
// baseline (speedup 1.0000x reference)
#include <cuda_runtime.h>
#include <cuda_bf16.h>

// Problem dims
#define B_    512
#define T_    1024
#define DIN_  64
#define H_    256
#define MLPH_ 256
#define DOUT_ 64

// ---------------- LSTM config ----------------
// 16 groups x 8 CTAs; group = 32 batch rows; CTA = 32 units = 128 gate cols
// 256 threads = 8 warps: ks = wid>>2 (K-half), ng = wid&3 (n32 slice)
// Warp tile m32 x n32 x K160. Plane-major fragment layout (conflict-free):
//  B block bb = kt*4 + ng (80 x 512 u32), A block = kt*2 + mt (40 x 256 u32)
#define KT_     20
#define OFF_A   40960
#define RED_OFF 51200                         // 4096 f32 reduction buffer
#define LSTM_SMEM_BYTES ((51200 + 4096) * 4)  // 221184

// ---------------- MLP config (proven R14) ----------------
#define MW_OFF 16384
#define W2_OFF 32768
#define MLP_SMEM_BYTES (49152 * 4)    // 196608

// Device scratch (static; cudaMalloc forbidden)
__device__ float    g_hs[(size_t)B_ * T_ * H_];          // hidden states (MLP input)
__device__ unsigned g_hfrag[2][16][32][256];             // h frags, double-buffered
__device__ unsigned g_xfrag[(size_t)T_ * 16 * 8 * 256];  // x frags (all t)
__device__ unsigned g_bar[16];

__device__ __forceinline__ float sigf(float v) {
    return __fdividef(1.0f, 1.0f + __expf(-v));
}
__device__ __forceinline__ float tfast(float v) {
    float e = __expf(-2.0f * fabsf(v));
    return copysignf(__fdividef(1.0f - e, 1.0f + e), v);
}

__device__ __forceinline__ void mma16816(float* c, const unsigned* a, const unsigned* b) {
    asm volatile(
        "mma.sync.aligned.m16n8k16.row.col.f32.bf16.bf16.f32 "
        "{%0,%1,%2,%3},{%4,%5,%6,%7},{%8,%9},{%0,%1,%2,%3};\n"
        : "+f"(c[0]), "+f"(c[1]), "+f"(c[2]), "+f"(c[3])
        : "r"(a[0]), "r"(a[1]), "r"(a[2]), "r"(a[3]), "r"(b[0]), "r"(b[1]));
}

__device__ __forceinline__ void split_pack(float2 v, unsigned& uhi, unsigned& ulo) {
    __nv_bfloat16 hx = __float2bfloat16(v.x);
    __nv_bfloat16 hy = __float2bfloat16(v.y);
    __nv_bfloat16 lx = __float2bfloat16(v.x - __bfloat162float(hx));
    __nv_bfloat16 ly = __float2bfloat16(v.y - __bfloat162float(hy));
    uhi = (unsigned)__bfloat16_as_ushort(hx) | ((unsigned)__bfloat16_as_ushort(hy) << 16);
    ulo = (unsigned)__bfloat16_as_ushort(lx) | ((unsigned)__bfloat16_as_ushort(ly) << 16);
}

// ---------------------------------------------------------------------------
// init: pack h0 into fragment layout (phase 0), reset barriers.
// ---------------------------------------------------------------------------
__global__ void init_kernel(const float* __restrict__ h0) {
    unsigned s = blockIdx.x * 256 + threadIdx.x;   // 0..16383
    int ln = s & 31, blk = (s >> 5) & 31, p = (s >> 10) & 15;
    int kt = blk >> 1, mt = blk & 1, gid = ln >> 2, tg = ln & 3;
    unsigned hi[4], lo[4];
#pragma unroll
    for (int r = 0; r < 4; r++) {
        int row = p * 32 + mt * 16 + gid + (r & 1) * 8;
        int un  = kt * 16 + tg * 2 + (r >> 1) * 8;
        float2 v = *(const float2*)&h0[(size_t)row * H_ + un];
        split_pack(v, hi[r], lo[r]);
    }
    unsigned* dst = &g_hfrag[0][p][blk][ln * 4];
    *(uint4*)dst         = make_uint4(hi[0], hi[1], hi[2], hi[3]);
    *(uint4*)(dst + 128) = make_uint4(lo[0], lo[1], lo[2], lo[3]);
    if (s < 16) g_bar[s] = 0u;
}

// ---------------------------------------------------------------------------
// xfrag: pack x for ALL timesteps into fragment layout. grid 16384 x 256.
// ---------------------------------------------------------------------------
__global__ void xfrag_kernel(const float* __restrict__ x) {
    unsigned s = blockIdx.x * 256 + threadIdx.x;
    int ln = s & 31, blkx = (s >> 5) & 7, p = (s >> 8) & 15, t = s >> 12;
    int kt = blkx >> 1, mt = blkx & 1, gid = ln >> 2, tg = ln & 3;
    unsigned hi[4], lo[4];
#pragma unroll
    for (int r = 0; r < 4; r++) {
        int row = p * 32 + mt * 16 + gid + (r & 1) * 8;
        int kb  = kt * 16 + tg * 2 + (r >> 1) * 8;
        float2 v = *(const float2*)&x[((size_t)row * T_ + t) * DIN_ + kb];
        split_pack(v, hi[r], lo[r]);
    }
    unsigned* dst = g_xfrag + ((((size_t)t * 16 + p) * 8 + blkx) << 8) + ln * 4;
    *(uint4*)dst         = make_uint4(hi[0], hi[1], hi[2], hi[3]);
    *(uint4*)(dst + 128) = make_uint4(lo[0], lo[1], lo[2], lo[3]);
}

// ---------------------------------------------------------------------------
// Persistent LSTM. grid 128 (16 groups x 8), 256 threads.
// 8 warps: ks = wid>>2 (K-half of 10 kt), ng = wid&3. Warp tile m32n32.
// ---------------------------------------------------------------------------
#define LOADFRAG(kt, bf) do {                                                  \
    const unsigned* _a = smU + OFF_A + (kt) * 512 + lane * 4;                  \
    *(uint4*)(ah[bf][0]) = *(const uint4*)(_a);                                \
    *(uint4*)(al[bf][0]) = *(const uint4*)(_a + 128);                          \
    *(uint4*)(ah[bf][1]) = *(const uint4*)(_a + 256);                          \
    *(uint4*)(al[bf][1]) = *(const uint4*)(_a + 384);                          \
    const unsigned* _b = smU + ((kt) * 4 + ng) * 512 + lane * 4;               \
    *(uint4*)(bh[bf])     = *(const uint4*)(_b);                               \
    *(uint4*)(bh[bf] + 4) = *(const uint4*)(_b + 128);                         \
    *(uint4*)(bl[bf])     = *(const uint4*)(_b + 256);                         \
    *(uint4*)(bl[bf] + 4) = *(const uint4*)(_b + 384);                         \
} while (0)

#define MMASTEP(bf) do {                                                       \
    _Pragma("unroll")                                                          \
    for (int mt = 0; mt < 2; mt++) {                                           \
        _Pragma("unroll")                                                      \
        for (int j = 0; j < 4; j++) {                                          \
            mma16816(acc[mt][j], ah[bf][mt], bh[bf] + j * 2);                  \
            mma16816(acc[mt][j], ah[bf][mt], bl[bf] + j * 2);                  \
            mma16816(acc[mt][j], al[bf][mt], bh[bf] + j * 2);                  \
        }                                                                      \
    }                                                                          \
} while (0)

__global__ void __launch_bounds__(256, 1) lstm_kernel(
    const float* __restrict__ c0,   const float* __restrict__ W_ih,
    const float* __restrict__ W_hh, const float* __restrict__ b_ih,
    const float* __restrict__ b_hh)
{
    extern __shared__ unsigned smU[];
    float* redf = (float*)(smU + RED_OFF);

    const int tid  = threadIdx.x;
    const int p    = blockIdx.x >> 3;
    const int q    = blockIdx.x & 7;
    const int b0   = p * 32;
    const int u0   = q * 32;
    const int lane = tid & 31;
    const int wid  = tid >> 5;
    const int ks   = wid >> 2;        // K-half 0..1
    const int ng   = wid & 3;         // n-group 0..3 (32 gate cols)
    const int gid  = lane >> 2;
    const int tg   = lane & 3;
    const int rc   = ng * 32 + lane;  // reduction column 0..127

    // ---- one-time: fragment-pack weight slice (hi+lo, plane-major) ----
    for (int s = tid; s < 20480; s += 256) {
        int w  = s & 7;                  // j*2 + r
        int ln = (s >> 3) & 31;
        int bb = s >> 8;                 // kt*4 + bng
        int j = w >> 1, r = w & 1;
        int bng = bb & 3, kt = bb >> 2;
        int grow = j * H_ + u0 + bng * 8 + (ln >> 2);
        int k    = kt * 16 + (ln & 3) * 2 + r * 8;
        float2 wv = (k < H_) ? *(const float2*)&W_hh[(size_t)grow * H_ + k]
                             : *(const float2*)&W_ih[(size_t)grow * DIN_ + (k - H_)];
        unsigned uhi, ulo;
        split_pack(wv, uhi, ulo);
        int a = bb * 512 + (w >> 2) * 128 + ln * 4 + (w & 3);
        smU[a]       = uhi;
        smU[a + 256] = ulo;
    }

    // bias (ks0 seeds acc with it; ks1 seeds 0) + cell state (ks0 only)
    float bs[4][2];
#pragma unroll
    for (int j = 0; j < 4; j++)
#pragma unroll
        for (int e = 0; e < 2; e++) {
            int un = u0 + ng * 8 + tg * 2 + e;
            bs[j][e] = (ks == 0) ? (b_ih[j * H_ + un] + b_hh[j * H_ + un]) : 0.0f;
        }
    float cst[8];
#pragma unroll
    for (int i = 0; i < 8; i++) cst[i] = 0.0f;
    if (ks == 0) {
#pragma unroll
        for (int mt = 0; mt < 2; mt++)
#pragma unroll
            for (int rr = 0; rr < 4; rr++) {
                int row = b0 + mt * 16 + gid + (rr >> 1) * 8;
                int un  = u0 + ng * 8 + tg * 2 + (rr & 1);
                cst[mt * 4 + rr] = c0[(size_t)row * H_ + un];
            }
    }
    __syncthreads();

    const int k0    = ks * 10;
    const int ucol  = u0 + ng * 8 + tg * 2;

    for (int t = 0; t < T_; t++) {
        // ---- x-frag copy first (independent of barrier; overlaps spin) ----
        const unsigned* xsrc = g_xfrag + (((size_t)t * 16 + p) << 11);
        for (int i4 = tid; i4 < 512; i4 += 256)
            *(uint4*)&smU[OFF_A + 8192 + i4 * 4] = __ldcg((const uint4*)(xsrc + i4 * 4));

        // ---- wait for h_t from all 8 CTAs ----
        if (t > 0 && tid == 0) {
            unsigned target = 8u * (unsigned)t;
            unsigned v;
            do {
                asm volatile("ld.global.acquire.gpu.u32 %0, [%1];"
                             : "=r"(v) : "l"(g_bar + p));
            } while (v < target);
        }
        __syncthreads();

        // ---- h-frag copy ----
        const unsigned* hsrc = &g_hfrag[t & 1][p][0][0];
        for (int i4 = tid; i4 < 2048; i4 += 256)
            *(uint4*)&smU[OFF_A + i4 * 4] = __ldcg((const uint4*)(hsrc + i4 * 4));
        __syncthreads();

        // ---- GEMM: this warp's K-half, 3-pass bf16 split, double-buffered ----
        float acc[2][4][4];
#pragma unroll
        for (int mt = 0; mt < 2; mt++)
#pragma unroll
            for (int j = 0; j < 4; j++)
#pragma unroll
                for (int rr = 0; rr < 4; rr++) acc[mt][j][rr] = bs[j][rr & 1];

        unsigned ah[2][2][4], al[2][2][4], bh[2][8], bl[2][8];
        LOADFRAG(k0, 0);
#pragma unroll 2
        for (int kk = 0; kk < 10; kk++) {
            int bf = kk & 1;
            if (kk + 1 < 10) LOADFRAG(k0 + kk + 1, bf ^ 1);
            MMASTEP(bf);
        }

        // ---- K-split reduction: ks1 stores partials, ks0 adds ----
        if (ks == 1) {
#pragma unroll
            for (int mt = 0; mt < 2; mt++)
#pragma unroll
                for (int j = 0; j < 4; j++)
#pragma unroll
                    for (int rr = 0; rr < 4; rr++)
                        redf[(mt * 16 + j * 4 + rr) * 128 + rc] = acc[mt][j][rr];
        }
        __syncthreads();

        int nb = (t + 1) & 1;
        float hv[2][4];
        if (ks == 0) {
#pragma unroll
            for (int mt = 0; mt < 2; mt++)
#pragma unroll
                for (int j = 0; j < 4; j++)
#pragma unroll
                    for (int rr = 0; rr < 4; rr++)
                        acc[mt][j][rr] += redf[(mt * 16 + j * 4 + rr) * 128 + rc];

            // ---- pointwise LSTM cell ----
#pragma unroll
            for (int mt = 0; mt < 2; mt++)
#pragma unroll
                for (int rr = 0; rr < 4; rr++) {
                    float ig = sigf(acc[mt][0][rr]);
                    float fg = sigf(acc[mt][1][rr]);
                    float gg = tfast(acc[mt][2][rr]);
                    float og = sigf(acc[mt][3][rr]);
                    float cn = fmaf(fg, cst[mt * 4 + rr], ig * gg);
                    cst[mt * 4 + rr] = cn;
                    hv[mt][rr] = og * tfast(cn);
                }
            // h -> fragment layout in global (plane-major)
#pragma unroll
            for (int mt = 0; mt < 2; mt++)
#pragma unroll
                for (int s = 0; s < 2; s++) {
                    unsigned uhi, ulo;
                    split_pack(make_float2(hv[mt][s * 2], hv[mt][s * 2 + 1]), uhi, ulo);
                    int blk = (q * 2 + (ng >> 1)) * 2 + mt;
                    int rA = s | ((ng & 1) << 1);
                    unsigned* d = &g_hfrag[nb][p][blk][lane * 4 + rA];
                    d[0]   = uhi;
                    d[128] = ulo;
                }
        }

        // ---- release (bar.sync orders all threads' stores before it) ----
        __syncthreads();
        if (tid == 0)
            asm volatile("red.release.gpu.global.add.u32 [%0], %1;"
                         :: "l"(g_bar + p), "r"(1u) : "memory");

        // ---- g_hs writeout (off inter-CTA critical path) ----
        if (ks == 0) {
#pragma unroll
            for (int mt = 0; mt < 2; mt++) {
                int row = b0 + mt * 16 + gid;
                *(float2*)&g_hs[((size_t)row * T_ + t) * H_ + ucol] =
                    make_float2(hv[mt][0], hv[mt][1]);
                *(float2*)&g_hs[((size_t)(row + 8) * T_ + t) * H_ + ucol] =
                    make_float2(hv[mt][2], hv[mt][3]);
            }
        }
    }
}

// ---------------------------------------------------------------------------
// MLP with bf16x3 tensor cores (proven R14): y = relu(hs@W1^T+b1)@W2^T+b2, *mask
// grid 4096 (128-row tiles), 512 threads = 16 warps (mw = wid&7, nh = wid>>3)
// ---------------------------------------------------------------------------
__global__ void __launch_bounds__(512, 1) mlp_kernel(
    const float* __restrict__ W1, const float* __restrict__ b1,
    const float* __restrict__ W2, const float* __restrict__ b2,
    const float* __restrict__ mask, float* __restrict__ out)
{
    extern __shared__ unsigned smU[];

    const int tid  = threadIdx.x;
    const int lane = tid & 31;
    const int wid  = tid >> 5;
    const int gid  = lane >> 2;
    const int tg   = lane & 3;
    const int mw   = wid & 7;
    const int nh   = wid >> 3;
    const size_t row0 = (size_t)blockIdx.x * 128;

    float acc[4][4][4];
#pragma unroll
    for (int bg = 0; bg < 4; bg++)
#pragma unroll
        for (int j = 0; j < 4; j++)
#pragma unroll
            for (int rr = 0; rr < 4; rr++) acc[bg][j][rr] = 0.0f;

    // ---- GEMM1: 2 k-chunks of 128 ----
    for (int c = 0; c < 2; c++) {
        for (int s = tid; s < 8192; s += 512) {
            int r = s & 3, ln = (s >> 2) & 31, ab = s >> 7;
            int mt = ab & 7, kt = ab >> 3;
            size_t row = row0 + mt * 16 + (ln >> 2) + (r & 1) * 8;
            int k = c * 128 + kt * 16 + (ln & 3) * 2 + (r >> 1) * 8;
            float2 v = *(const float2*)&g_hs[row * H_ + k];
            unsigned uhi, ulo;
            split_pack(v, uhi, ulo);
            smU[ab * 256 + ln * 4 + r]       = uhi;
            smU[ab * 256 + 128 + ln * 4 + r] = ulo;
        }
        for (int s = tid; s < 16384; s += 512) {
            int w = s & 7, ln = (s >> 3) & 31, wb = s >> 8;
            int bg = wb & 7, kt = wb >> 3;
            int n = bg * 32 + (w >> 1) * 8 + (ln >> 2);
            int k = c * 128 + kt * 16 + (ln & 3) * 2 + (w & 1) * 8;
            float2 v = *(const float2*)&W1[(size_t)n * H_ + k];
            unsigned uhi, ulo;
            split_pack(v, uhi, ulo);
            int a = MW_OFF + wb * 512 + (w >> 2) * 128 + ln * 4 + (w & 3);
            smU[a]       = uhi;
            smU[a + 256] = ulo;
        }
        __syncthreads();

        for (int kt = 0; kt < 8; kt++) {
            const unsigned* _a = smU + (kt * 8 + mw) * 256 + lane * 4;
            unsigned ah[4], al[4];
            *(uint4*)ah = *(const uint4*)_a;
            *(uint4*)al = *(const uint4*)(_a + 128);
#pragma unroll
            for (int bg = 0; bg < 4; bg++) {
                const unsigned* _b = smU + MW_OFF + (kt * 8 + nh * 4 + bg) * 512 + lane * 4;
                unsigned bh[8], bl[8];
                *(uint4*)(bh)     = *(const uint4*)(_b);
                *(uint4*)(bh + 4) = *(const uint4*)(_b + 128);
                *(uint4*)(bl)     = *(const uint4*)(_b + 256);
                *(uint4*)(bl + 4) = *(const uint4*)(_b + 384);
#pragma unroll
                for (int j = 0; j < 4; j++) {
                    mma16816(acc[bg][j], ah, bh + j * 2);
                    mma16816(acc[bg][j], ah, bl + j * 2);
                    mma16816(acc[bg][j], al, bh + j * 2);
                }
            }
        }
        __syncthreads();
    }

    // ---- stage W2 ----
    for (int s = tid; s < 8192; s += 512) {
        int w = s & 7, ln = (s >> 3) & 31, wb = s >> 8;
        int bg2 = wb & 1, kt2 = wb >> 1;
        int n = bg2 * 32 + (w >> 1) * 8 + (ln >> 2);
        int k = kt2 * 16 + (ln & 3) * 2 + (w & 1) * 8;
        float2 v = *(const float2*)&W2[(size_t)n * MLPH_ + k];
        unsigned uhi, ulo;
        split_pack(v, uhi, ulo);
        int a = W2_OFF + wb * 512 + (w >> 2) * 128 + ln * 4 + (w & 3);
        smU[a]       = uhi;
        smU[a + 256] = ulo;
    }

    // ---- epilogue1: bias + relu -> y1 fragments ----
#pragma unroll
    for (int bg = 0; bg < 4; bg++)
#pragma unroll
        for (int j = 0; j < 4; j++) {
            int bgp = nh * 4 + bg;
            int colb = bgp * 32 + j * 8 + tg * 2;
            float ba = b1[colb], bbv = b1[colb + 1];
            float v00 = fmaxf(acc[bg][j][0] + ba, 0.0f);
            float v01 = fmaxf(acc[bg][j][1] + bbv, 0.0f);
            float v10 = fmaxf(acc[bg][j][2] + ba, 0.0f);
            float v11 = fmaxf(acc[bg][j][3] + bbv, 0.0f);
            int yb = (bgp * 2 + (j >> 1)) * 8 + mw;
            int rb = (j & 1) * 2;
            unsigned uhi, ulo;
            split_pack(make_float2(v00, v01), uhi, ulo);
            smU[yb * 256 + lane * 4 + rb]       = uhi;
            smU[yb * 256 + 128 + lane * 4 + rb] = ulo;
            split_pack(make_float2(v10, v11), uhi, ulo);
            smU[yb * 256 + lane * 4 + rb + 1]       = uhi;
            smU[yb * 256 + 128 + lane * 4 + rb + 1] = ulo;
        }
    __syncthreads();

    // ---- GEMM2: m128 n64 k256 ----
    float acc2[4][4];
#pragma unroll
    for (int j = 0; j < 4; j++)
#pragma unroll
        for (int rr = 0; rr < 4; rr++) acc2[j][rr] = 0.0f;

    for (int kt2 = 0; kt2 < 16; kt2++) {
        const unsigned* _a = smU + (kt2 * 8 + mw) * 256 + lane * 4;
        unsigned ah[4], al[4];
        *(uint4*)ah = *(const uint4*)_a;
        *(uint4*)al = *(const uint4*)(_a + 128);
        const unsigned* _b = smU + W2_OFF + (kt2 * 2 + nh) * 512 + lane * 4;
        unsigned bh[8], bl[8];
        *(uint4*)(bh)     = *(const uint4*)(_b);
        *(uint4*)(bh + 4) = *(const uint4*)(_b + 128);
        *(uint4*)(bl)     = *(const uint4*)(_b + 256);
        *(uint4*)(bl + 4) = *(const uint4*)(_b + 384);
#pragma unroll
        for (int j = 0; j < 4; j++) {
            mma16816(acc2[j], ah, bh + j * 2);
            mma16816(acc2[j], ah, bl + j * 2);
            mma16816(acc2[j], al, bh + j * 2);
        }
    }

    // ---- epilogue2: + b2, * mask, store ----
    size_t r0 = row0 + mw * 16 + gid;
    size_t r1 = r0 + 8;
    float m0 = mask[r0], m1 = mask[r1];
#pragma unroll
    for (int j = 0; j < 4; j++) {
        int col = nh * 32 + j * 8 + tg * 2;
        float bb0 = b2[col], bb1 = b2[col + 1];
        *(float2*)&out[r0 * DOUT_ + col] =
            make_float2((acc2[j][0] + bb0) * m0, (acc2[j][1] + bb1) * m0);
        *(float2*)&out[r1 * DOUT_ + col] =
            make_float2((acc2[j][2] + bb0) * m1, (acc2[j][3] + bb1) * m1);
    }
}

// ---------------------------------------------------------------------------
extern "C" void kernel_launch(void* const* d_in, const int* in_sizes, int n_in,
                              void* d_out, int out_size) {
    const float* x    = (const float*)d_in[0];
    const float* mask = (const float*)d_in[1];
    const float* h0   = (const float*)d_in[2];
    const float* c0   = (const float*)d_in[3];
    const float* W_ih = (const float*)d_in[4];
    const float* W_hh = (const float*)d_in[5];
    const float* b_ih = (const float*)d_in[6];
    const float* b_hh = (const float*)d_in[7];
    const float* W1   = (const float*)d_in[8];
    const float* b1   = (const float*)d_in[9];
    const float* W2   = (const float*)d_in[10];
    const float* b2   = (const float*)d_in[11];
    float* out = (float*)d_out;

    cudaFuncSetAttribute(lstm_kernel, cudaFuncAttributeMaxDynamicSharedMemorySize,
                         LSTM_SMEM_BYTES);
    cudaFuncSetAttribute(mlp_kernel, cudaFuncAttributeMaxDynamicSharedMemorySize,
                         MLP_SMEM_BYTES);

    init_kernel<<<64, 256>>>(h0);
    xfrag_kernel<<<16384, 256>>>(x);
    lstm_kernel<<<128, 256, LSTM_SMEM_BYTES>>>(c0, W_ih, W_hh, b_ih, b_hh);
    mlp_kernel<<<(B_ * T_) / 128, 512, MLP_SMEM_BYTES>>>(W1, b1, W2, b2, mask, out);
}